// round 1
// baseline (speedup 1.0000x reference)
#include <cuda_runtime.h>

#define C_IN  10
#define C_OUT 64
#define MAXM  200000
#define MAXPTS 64
#define W_BEV 512
#define H_BEV 512
#define FULLMASK 0xffffffffu

// ---- device scratch (no allocations allowed) ----
__device__ __align__(16) int   g_cnt[MAXM];             // points per pillar
__device__ __align__(16) int   g_order[MAXM * MAXPTS];  // bucketed point ids (51.2 MB)
__device__ float g_sum[C_OUT];
__device__ float g_sumsq[C_OUT];
__device__ float g_a[C_OUT];   // fused BN scale  = rstd*gamma
__device__ float g_b[C_OUT];   // fused BN shift  = beta - mu*rstd*gamma

// ---------------------------------------------------------------------------
// K1: zero canvas (float4), zero per-pillar counters and BN partial sums
// ---------------------------------------------------------------------------
__global__ void k_init(float4* __restrict__ out4, long long n4) {
    long long i = (long long)blockIdx.x * blockDim.x + threadIdx.x;
    long long stride = (long long)gridDim.x * blockDim.x;
    float4 z = make_float4(0.f, 0.f, 0.f, 0.f);
    for (long long j = i; j < n4; j += stride) out4[j] = z;
    int4* c4 = (int4*)g_cnt;
    for (long long j = i; j < MAXM / 4; j += stride) c4[j] = make_int4(0, 0, 0, 0);
    if (i < C_OUT) { g_sum[i] = 0.f; g_sumsq[i] = 0.f; }
}

// ---------------------------------------------------------------------------
// K2: one pass over points: h = x@W0 (pre-BN) column sums / sumsq for BN stats
//     + bucket-scatter point ids by pillar.
//     Warp-sliced: lane owns channels (2*lane, 2*lane+1).
// ---------------------------------------------------------------------------
__global__ void __launch_bounds__(256) k_stats(
    const float* __restrict__ gf, const int* __restrict__ psi,
    const float* __restrict__ W0, int N)
{
    const int lane = threadIdx.x & 31;
    const int warp = (blockIdx.x * blockDim.x + threadIdx.x) >> 5;
    const int nwarps = (gridDim.x * blockDim.x) >> 5;
    const int c0 = 2 * lane;

    float w0x[C_IN], w0y[C_IN];
#pragma unroll
    for (int k = 0; k < C_IN; k++) {
        float2 w = *(const float2*)(W0 + k * C_OUT + c0);
        w0x[k] = w.x; w0y[k] = w.y;
    }

    float sx = 0.f, sy = 0.f, qx = 0.f, qy = 0.f;
    for (int p = warp; p < N; p += nwarps) {
        float xv = (lane < C_IN) ? __ldg(gf + (long long)p * C_IN + lane) : 0.f;
        float hx = 0.f, hy = 0.f;
#pragma unroll
        for (int k = 0; k < C_IN; k++) {
            float xk = __shfl_sync(FULLMASK, xv, k);
            hx = fmaf(xk, w0x[k], hx);
            hy = fmaf(xk, w0y[k], hy);
        }
        sx += hx; sy += hy;
        qx = fmaf(hx, hx, qx); qy = fmaf(hy, hy, qy);
        if (lane == 0) {
            int idx = __ldg(psi + p);
            int pos = atomicAdd(&g_cnt[idx], 1);
            if (pos < MAXPTS) g_order[idx * MAXPTS + pos] = p;
        }
    }
    atomicAdd(&g_sum[c0],     sx); atomicAdd(&g_sum[c0 + 1],   sy);
    atomicAdd(&g_sumsq[c0],   qx); atomicAdd(&g_sumsq[c0 + 1], qy);
}

// ---------------------------------------------------------------------------
// K3: finalize BN affine params (train-mode batch stats, biased var)
// ---------------------------------------------------------------------------
__global__ void k_bn(const float* __restrict__ gamma, const float* __restrict__ beta,
                     float invN)
{
    int c = threadIdx.x;
    if (c < C_OUT) {
        float mu  = g_sum[c] * invN;
        float var = fmaf(-mu, mu, g_sumsq[c] * invN);
        float rstd = rsqrtf(var + 1e-3f);
        float a = rstd * gamma[c];
        g_a[c] = a;
        g_b[c] = fmaf(-mu, a, beta[c]);
    }
}

// ---------------------------------------------------------------------------
// K4: warp-per-pillar: for each of its points recompute h (BN+ReLU), compute
//     s = relu(h@Ws+bs) via warp shuffles, online-softmax accumulate
//     numerator / denominator / running h-max, then write
//     0.5*(num/den + hmax) straight into the BEV canvas.
// ---------------------------------------------------------------------------
__global__ void __launch_bounds__(256) k_pillar(
    const float* __restrict__ gf, const int* __restrict__ pind,
    const float* __restrict__ W0, const float* __restrict__ Ws,
    const float* __restrict__ bs, float* __restrict__ out, int M)
{
    const int lane = threadIdx.x & 31;
    const int pillar = (blockIdx.x * blockDim.x + threadIdx.x) >> 5;
    if (pillar >= M) return;
    const int c0 = 2 * lane;

    // per-lane weight slices (register resident; L1-hot loads)
    float w0x[C_IN], w0y[C_IN];
#pragma unroll
    for (int k = 0; k < C_IN; k++) {
        float2 w = *(const float2*)(W0 + k * C_OUT + c0);
        w0x[k] = w.x; w0y[k] = w.y;
    }
    float wsx[C_OUT], wsy[C_OUT];
#pragma unroll
    for (int k = 0; k < C_OUT; k++) {
        float2 w = *(const float2*)(Ws + k * C_OUT + c0);
        wsx[k] = w.x; wsy[k] = w.y;
    }
    const float2 bs2 = *(const float2*)(bs + c0);
    const float ax = g_a[c0], ay = g_a[c0 + 1];
    const float bx = g_b[c0], by = g_b[c0 + 1];

    const int cnt = min(g_cnt[pillar], MAXPTS);
    const int* __restrict__ ord = g_order + pillar * MAXPTS;

    float denx = 0.f, deny = 0.f;      // softmax denominators
    float numx = 0.f, numy = 0.f;      // softmax-weighted h sums
    float mxsx = 0.f, mxsy = 0.f;      // running max of s   (s >= 0 after relu)
    float mxhx = 0.f, mxhy = 0.f;      // running max of h   (h >= 0 after relu)

    for (int j = 0; j < cnt; j++) {
        int p = __ldg(ord + j);
        float xv = (lane < C_IN) ? __ldg(gf + (long long)p * C_IN + lane) : 0.f;

        // h = relu(BN(x @ W0)) for this lane's two channels
        float hx = 0.f, hy = 0.f;
#pragma unroll
        for (int k = 0; k < C_IN; k++) {
            float xk = __shfl_sync(FULLMASK, xv, k);
            hx = fmaf(xk, w0x[k], hx);
            hy = fmaf(xk, w0y[k], hy);
        }
        hx = fmaxf(fmaf(hx, ax, bx), 0.f);
        hy = fmaxf(fmaf(hy, ay, by), 0.f);

        // s = relu(h @ Ws + bs) : broadcast full 64-wide h via shuffles
        float s_x = bs2.x, s_y = bs2.y;
#pragma unroll
        for (int kk = 0; kk < 32; kk++) {
            float h0 = __shfl_sync(FULLMASK, hx, kk);
            float h1 = __shfl_sync(FULLMASK, hy, kk);
            s_x = fmaf(h0, wsx[2 * kk],     s_x);
            s_y = fmaf(h0, wsy[2 * kk],     s_y);
            s_x = fmaf(h1, wsx[2 * kk + 1], s_x);
            s_y = fmaf(h1, wsy[2 * kk + 1], s_y);
        }
        s_x = fmaxf(s_x, 0.f);
        s_y = fmaxf(s_y, 0.f);

        // online softmax accumulate (exact, overflow-safe)
        {
            float nm = fmaxf(mxsx, s_x);
            float e  = __expf(s_x - nm);
            float cr = __expf(mxsx - nm);
            denx = fmaf(denx, cr, e);
            numx = fmaf(numx, cr, e * hx);
            mxsx = nm;
        }
        {
            float nm = fmaxf(mxsy, s_y);
            float e  = __expf(s_y - nm);
            float cr = __expf(mxsy - nm);
            deny = fmaf(deny, cr, e);
            numy = fmaf(numy, cr, e * hy);
            mxsy = nm;
        }
        mxhx = fmaxf(mxhx, hx);
        mxhy = fmaxf(mxhy, hy);
    }

    float pfx = 0.5f * (numx / denx + mxhx);
    float pfy = 0.5f * (numy / deny + mxhy);
    if (cnt == 0) { pfx = 0.f; pfy = 0.f; }   // cannot happen per spec; NaN guard

    const int b = pind[pillar * 3 + 0];
    const int x = pind[pillar * 3 + 1];
    const int y = pind[pillar * 3 + 2];
    long long base = ((((long long)b * C_OUT + c0) * W_BEV + x) * H_BEV) + y;
    out[base] = pfx;
    out[base + (long long)W_BEV * H_BEV] = pfy;
}

// ---------------------------------------------------------------------------
extern "C" void kernel_launch(void* const* d_in, const int* in_sizes, int n_in,
                              void* d_out, int out_size)
{
    const float* gf    = (const float*)d_in[0];  // group_features   (N, 10)
    const int*   psi   = (const int*)  d_in[1];  // pillar_set_indices (N)
    const int*   pind  = (const int*)  d_in[2];  // pillar_indices   (M, 3)
    const float* W0    = (const float*)d_in[3];  // (10, 64)
    const float* gamma = (const float*)d_in[4];  // (64)
    const float* beta  = (const float*)d_in[5];  // (64)
    const float* Ws    = (const float*)d_in[6];  // (64, 64)
    const float* bs    = (const float*)d_in[7];  // (64)
    float* out = (float*)d_out;

    const int N = in_sizes[0] / C_IN;
    const int M = in_sizes[2] / 3;

    k_init<<<4096, 256>>>((float4*)out, (long long)out_size / 4);
    k_stats<<<2368, 256>>>(gf, psi, W0, N);
    k_bn<<<1, 64>>>(gamma, beta, 1.0f / (float)N);
    k_pillar<<<(M + 7) / 8, 256>>>(gf, pind, W0, Ws, bs, out, M);
}

// round 2
// speedup vs baseline: 1.4893x; 1.4893x over previous
#include <cuda_runtime.h>

#define C_IN  10
#define C_OUT 64
#define MAXM  200000
#define MAXPTS 64
#define W_BEV 512
#define H_BEV 512
#define FULLMASK 0xffffffffu

// ---- device scratch (no allocations allowed) ----
__device__ __align__(16) int   g_cnt[MAXM];             // points per pillar
__device__ __align__(16) int   g_order[MAXM * MAXPTS];  // bucketed point ids (51.2 MB)
__device__ float g_sum[C_OUT];
__device__ float g_sumsq[C_OUT];
__device__ float g_a[C_OUT];   // fused BN scale  = rstd*gamma
__device__ float g_b[C_OUT];   // fused BN shift  = beta - mu*rstd*gamma

// ---- packed f32x2 helpers (sm_100+ FFMA2; ptxas will not auto-fuse) ----
typedef unsigned long long u64;
__device__ __forceinline__ u64 pk2(float lo, float hi) {
    u64 r; asm("mov.b64 %0, {%1,%2};" : "=l"(r) : "f"(lo), "f"(hi)); return r;
}
__device__ __forceinline__ void upk2(u64 v, float& lo, float& hi) {
    asm("mov.b64 {%0,%1}, %2;" : "=f"(lo), "=f"(hi) : "l"(v));
}
__device__ __forceinline__ u64 fma2(u64 a, u64 b, u64 c) {
    u64 d; asm("fma.rn.f32x2 %0, %1, %2, %3;" : "=l"(d) : "l"(a), "l"(b), "l"(c)); return d;
}

// ---------------------------------------------------------------------------
// K1: zero canvas (float4), zero per-pillar counters and BN partial sums
// ---------------------------------------------------------------------------
__global__ void k_init(float4* __restrict__ out4, long long n4) {
    long long i = (long long)blockIdx.x * blockDim.x + threadIdx.x;
    long long stride = (long long)gridDim.x * blockDim.x;
    float4 z = make_float4(0.f, 0.f, 0.f, 0.f);
    for (long long j = i; j < n4; j += stride) out4[j] = z;
    int4* c4 = (int4*)g_cnt;
    for (long long j = i; j < MAXM / 4; j += stride) c4[j] = make_int4(0, 0, 0, 0);
    if (i < C_OUT) { g_sum[i] = 0.f; g_sumsq[i] = 0.f; }
}

// ---------------------------------------------------------------------------
// K2: one pass over points: pre-BN h column sums/sumsq + bucket-scatter ids
// ---------------------------------------------------------------------------
__global__ void __launch_bounds__(256) k_stats(
    const float* __restrict__ gf, const int* __restrict__ psi,
    const float* __restrict__ W0, int N)
{
    const int lane = threadIdx.x & 31;
    const int warp = (blockIdx.x * blockDim.x + threadIdx.x) >> 5;
    const int nwarps = (gridDim.x * blockDim.x) >> 5;
    const int c0 = 2 * lane;

    float w0x[C_IN], w0y[C_IN];
#pragma unroll
    for (int k = 0; k < C_IN; k++) {
        float2 w = *(const float2*)(W0 + k * C_OUT + c0);
        w0x[k] = w.x; w0y[k] = w.y;
    }

    float sx = 0.f, sy = 0.f, qx = 0.f, qy = 0.f;
    for (int p = warp; p < N; p += nwarps) {
        float xv = (lane < C_IN) ? __ldg(gf + (long long)p * C_IN + lane) : 0.f;
        float hx = 0.f, hy = 0.f;
#pragma unroll
        for (int k = 0; k < C_IN; k++) {
            float xk = __shfl_sync(FULLMASK, xv, k);
            hx = fmaf(xk, w0x[k], hx);
            hy = fmaf(xk, w0y[k], hy);
        }
        sx += hx; sy += hy;
        qx = fmaf(hx, hx, qx); qy = fmaf(hy, hy, qy);
        if (lane == 0) {
            int idx = __ldg(psi + p);
            int pos = atomicAdd(&g_cnt[idx], 1);
            if (pos < MAXPTS) g_order[idx * MAXPTS + pos] = p;
        }
    }
    atomicAdd(&g_sum[c0],     sx); atomicAdd(&g_sum[c0 + 1],   sy);
    atomicAdd(&g_sumsq[c0],   qx); atomicAdd(&g_sumsq[c0 + 1], qy);
}

// ---------------------------------------------------------------------------
// K3: finalize BN affine params (train-mode batch stats, biased var)
// ---------------------------------------------------------------------------
__global__ void k_bn(const float* __restrict__ gamma, const float* __restrict__ beta,
                     float invN)
{
    int c = threadIdx.x;
    if (c < C_OUT) {
        float mu  = g_sum[c] * invN;
        float var = fmaf(-mu, mu, g_sumsq[c] * invN);
        float rstd = rsqrtf(var + 1e-3f);
        float a = rstd * gamma[c];
        g_a[c] = a;
        g_b[c] = fmaf(-mu, a, beta[c]);
    }
}

// ---------------------------------------------------------------------------
// K4: one warp (= one 32-thread block) per pillar.
//     Per point: recompute h (BN+ReLU), s = relu(h@Ws+bs) via shuffle-broadcast
//     with Ws register-stationary as f32x2 pairs, single-exp online softmax,
//     then write 0.5*(num/den + hmax) straight into the BEV canvas.
// ---------------------------------------------------------------------------
__global__ void __launch_bounds__(32) k_pillar(
    const float* __restrict__ gf, const int* __restrict__ pind,
    const float* __restrict__ W0, const float* __restrict__ Ws,
    const float* __restrict__ bs, float* __restrict__ out, int M)
{
    const int lane = threadIdx.x & 31;
    const int pillar = blockIdx.x;
    if (pillar >= M) return;
    const int c0 = 2 * lane;

    // W0 column pair for this lane, packed
    u64 w0v[C_IN];
#pragma unroll
    for (int k = 0; k < C_IN; k++) {
        float2 w = *(const float2*)(W0 + k * C_OUT + c0);
        w0v[k] = pk2(w.x, w.y);
    }
    // Ws column pair for this lane, packed over k-pairs:
    //   wsxv[j] = (Ws[2j][c0],   Ws[2j+1][c0])
    //   wsyv[j] = (Ws[2j][c0+1], Ws[2j+1][c0+1])
    u64 wsxv[32], wsyv[32];
#pragma unroll
    for (int j = 0; j < 32; j++) {
        float2 wa = *(const float2*)(Ws + (2 * j)     * C_OUT + c0);
        float2 wb = *(const float2*)(Ws + (2 * j + 1) * C_OUT + c0);
        wsxv[j] = pk2(wa.x, wb.x);
        wsyv[j] = pk2(wa.y, wb.y);
    }
    const float2 bs2 = *(const float2*)(bs + c0);
    const u64 av = pk2(g_a[c0], g_a[c0 + 1]);
    const u64 bv = pk2(g_b[c0], g_b[c0 + 1]);

    const int cnt = min(g_cnt[pillar], MAXPTS);
    const int* __restrict__ ord = g_order + pillar * MAXPTS;

    float denx = 0.f, deny = 0.f;      // softmax denominators
    float numx = 0.f, numy = 0.f;      // softmax-weighted h sums
    float mxsx = 0.f, mxsy = 0.f;      // running max of s   (s >= 0 after relu)
    float mxhx = 0.f, mxhy = 0.f;      // running max of h   (h >= 0 after relu)

    // software pipeline: prefetch point id + feature one iteration ahead
    int   p_cur  = (cnt > 0) ? __ldg(ord + 0) : 0;
    float xv_cur = (lane < C_IN) ? __ldg(gf + (long long)p_cur * C_IN + lane) : 0.f;

    for (int j = 0; j < cnt; j++) {
        float xv = xv_cur;
        if (j + 1 < cnt) {
            int p_nxt = __ldg(ord + j + 1);
            xv_cur = (lane < C_IN) ? __ldg(gf + (long long)p_nxt * C_IN + lane) : 0.f;
        }

        // h = relu(BN(x @ W0)) for this lane's two channels (packed)
        u64 hv = 0;  // (0.f, 0.f)
#pragma unroll
        for (int k = 0; k < C_IN; k++) {
            float xk = __shfl_sync(FULLMASK, xv, k);
            hv = fma2(pk2(xk, xk), w0v[k], hv);
        }
        hv = fma2(hv, av, bv);
        float hx, hy; upk2(hv, hx, hy);
        hx = fmaxf(hx, 0.f);
        hy = fmaxf(hy, 0.f);

        // s = relu(h @ Ws + bs): broadcast the 64-wide h by shuffling (hx, hy)
        // sxv accumulates channel c0 split over (even-k, odd-k); syv for c0+1
        u64 sxv = pk2(bs2.x, 0.f);
        u64 syv = pk2(bs2.y, 0.f);
#pragma unroll
        for (int j2 = 0; j2 < 32; j2++) {
            float h0 = __shfl_sync(FULLMASK, hx, j2);
            float h1 = __shfl_sync(FULLMASK, hy, j2);
            u64 hj = pk2(h0, h1);
            sxv = fma2(hj, wsxv[j2], sxv);
            syv = fma2(hj, wsyv[j2], syv);
        }
        float sxa, sxb, sya, syb;
        upk2(sxv, sxa, sxb); upk2(syv, sya, syb);
        float s_x = fmaxf(sxa + sxb, 0.f);
        float s_y = fmaxf(sya + syb, 0.f);

        // single-exp online softmax: exp(-|s-m|) is the only exp needed,
        // the other factor is exp(0)=1 by construction.
        {
            float d  = s_x - mxsx;
            float e1 = __expf(-fabsf(d));
            bool  gt = d > 0.f;
            float fa = gt ? e1 : 1.f;
            float fb = gt ? 1.f : e1;
            denx = fmaf(denx, fa, fb);
            numx = fmaf(numx, fa, fb * hx);
            mxsx = fmaxf(mxsx, s_x);
        }
        {
            float d  = s_y - mxsy;
            float e1 = __expf(-fabsf(d));
            bool  gt = d > 0.f;
            float fa = gt ? e1 : 1.f;
            float fb = gt ? 1.f : e1;
            deny = fmaf(deny, fa, fb);
            numy = fmaf(numy, fa, fb * hy);
            mxsy = fmaxf(mxsy, s_y);
        }
        mxhx = fmaxf(mxhx, hx);
        mxhy = fmaxf(mxhy, hy);
    }

    float pfx = 0.5f * (numx / denx + mxhx);
    float pfy = 0.5f * (numy / deny + mxhy);
    if (cnt == 0) { pfx = 0.f; pfy = 0.f; }   // cannot happen per spec; NaN guard

    const int b = __ldg(pind + pillar * 3 + 0);
    const int x = __ldg(pind + pillar * 3 + 1);
    const int y = __ldg(pind + pillar * 3 + 2);
    long long base = ((((long long)b * C_OUT + c0) * W_BEV + x) * H_BEV) + y;
    out[base] = pfx;
    out[base + (long long)W_BEV * H_BEV] = pfy;
}

// ---------------------------------------------------------------------------
extern "C" void kernel_launch(void* const* d_in, const int* in_sizes, int n_in,
                              void* d_out, int out_size)
{
    const float* gf    = (const float*)d_in[0];  // group_features   (N, 10)
    const int*   psi   = (const int*)  d_in[1];  // pillar_set_indices (N)
    const int*   pind  = (const int*)  d_in[2];  // pillar_indices   (M, 3)
    const float* W0    = (const float*)d_in[3];  // (10, 64)
    const float* gamma = (const float*)d_in[4];  // (64)
    const float* beta  = (const float*)d_in[5];  // (64)
    const float* Ws    = (const float*)d_in[6];  // (64, 64)
    const float* bs    = (const float*)d_in[7];  // (64)
    float* out = (float*)d_out;

    const int N = in_sizes[0] / C_IN;
    const int M = in_sizes[2] / 3;

    k_init<<<4096, 256>>>((float4*)out, (long long)out_size / 4);
    k_stats<<<2368, 256>>>(gf, psi, W0, N);
    k_bn<<<1, 64>>>(gamma, beta, 1.0f / (float)N);
    k_pillar<<<M, 32>>>(gf, pind, W0, Ws, bs, out, M);
}

// round 3
// speedup vs baseline: 1.6392x; 1.1007x over previous
#include <cuda_runtime.h>

#define C_IN   10
#define C_OUT  64
#define MAXM   200000
#define MAXN   2000000
#define MAXPTS 64
#define W_BEV  512
#define H_BEV  512
#define FULLMASK 0xffffffffu

// ---- device scratch (statics; no runtime allocation) ----
__device__ __align__(16) int   g_cnt[MAXM];
__device__ __align__(16) int   g_order[MAXM * MAXPTS];   // 51.2 MB
__device__ __align__(16) float g_s[(long long)MAXN * C_OUT]; // 512 MB: s = h@Ws + bs (pre-relu)
__device__ __align__(16) float g_sum[C_OUT];
__device__ __align__(16) float g_sumsq[C_OUT];
__device__ __align__(16) float g_a[C_OUT];   // rstd*gamma
__device__ __align__(16) float g_b[C_OUT];   // beta - mu*rstd*gamma

// ---- packed f32x2 helpers (sm_100+; ptxas won't auto-fuse) ----
typedef unsigned long long u64;
__device__ __forceinline__ u64 pk2(float lo, float hi) {
    u64 r; asm("mov.b64 %0, {%1,%2};" : "=l"(r) : "f"(lo), "f"(hi)); return r;
}
__device__ __forceinline__ void upk2(u64 v, float& lo, float& hi) {
    asm("mov.b64 {%0,%1}, %2;" : "=f"(lo), "=f"(hi) : "l"(v));
}
__device__ __forceinline__ u64 fma2(u64 a, u64 b, u64 c) {
    u64 d; asm("fma.rn.f32x2 %0, %1, %2, %3;" : "=l"(d) : "l"(a), "l"(b), "l"(c)); return d;
}
__device__ __forceinline__ u64 add2(u64 a, u64 b) {
    u64 d; asm("add.rn.f32x2 %0, %1, %2;" : "=l"(d) : "l"(a), "l"(b)); return d;
}

// ---------------------------------------------------------------------------
// K1: zero canvas + per-pillar counters + BN partials
// ---------------------------------------------------------------------------
__global__ void k_init(float4* __restrict__ out4, long long n4) {
    long long i = (long long)blockIdx.x * blockDim.x + threadIdx.x;
    long long stride = (long long)gridDim.x * blockDim.x;
    float4 z = make_float4(0.f, 0.f, 0.f, 0.f);
    for (long long j = i; j < n4; j += stride) out4[j] = z;
    int4* c4 = (int4*)g_cnt;
    for (long long j = i; j < MAXM / 4; j += stride) c4[j] = make_int4(0, 0, 0, 0);
    if (i < C_OUT) { g_sum[i] = 0.f; g_sumsq[i] = 0.f; }
}

// ---------------------------------------------------------------------------
// K2: BN batch stats of pre-BN h + bucket point ids by pillar.
//     Lane owns channels (2l, 2l+1); x row read via uniform float2 loads.
// ---------------------------------------------------------------------------
__global__ void __launch_bounds__(256) k_stats(
    const float* __restrict__ gf, const int* __restrict__ psi,
    const float* __restrict__ W0, int N)
{
    const int lane = threadIdx.x & 31;
    const int warp = (blockIdx.x * blockDim.x + threadIdx.x) >> 5;
    const int nwarps = (gridDim.x * blockDim.x) >> 5;
    const int c0 = 2 * lane;

    u64 w0v[C_IN];
#pragma unroll
    for (int k = 0; k < C_IN; k++) {
        float2 w = *(const float2*)(W0 + k * C_OUT + c0);
        w0v[k] = pk2(w.x, w.y);
    }

    u64 sv = 0, qv = 0;
    for (int p = warp; p < N; p += nwarps) {
        const float2* xr = (const float2*)(gf + (long long)p * C_IN);
        u64 hv = 0;
#pragma unroll
        for (int k2 = 0; k2 < C_IN / 2; k2++) {
            float2 x2 = __ldg(xr + k2);
            hv = fma2(pk2(x2.x, x2.x), w0v[2 * k2],     hv);
            hv = fma2(pk2(x2.y, x2.y), w0v[2 * k2 + 1], hv);
        }
        sv = add2(sv, hv);
        qv = fma2(hv, hv, qv);
        if (lane == 0) {
            int idx = __ldg(psi + p);
            int pos = atomicAdd(&g_cnt[idx], 1);
            if (pos < MAXPTS) g_order[idx * MAXPTS + pos] = p;
        }
    }
    float slo, shi, qlo, qhi;
    upk2(sv, slo, shi); upk2(qv, qlo, qhi);
    atomicAdd(&g_sum[c0],       slo); atomicAdd(&g_sum[c0 + 1],   shi);
    atomicAdd(&g_sumsq[c0],     qlo); atomicAdd(&g_sumsq[c0 + 1], qhi);
}

// ---------------------------------------------------------------------------
// K3: finalize BN affine params
// ---------------------------------------------------------------------------
__global__ void k_bn(const float* __restrict__ gamma, const float* __restrict__ beta,
                     float invN)
{
    int c = threadIdx.x;
    if (c < C_OUT) {
        float mu  = g_sum[c] * invN;
        float var = fmaf(-mu, mu, g_sumsq[c] * invN);
        float rstd = rsqrtf(var + 1e-3f);
        float a = rstd * gamma[c];
        g_a[c] = a;
        g_b[c] = fmaf(-mu, a, beta[c]);
    }
}

// ---------------------------------------------------------------------------
// K4: dense SGEMM pass: per 128-point tile, compute h = relu(BN(x@W0)) into
//     smem (transposed, padded stride), then s = h@Ws + bs with FFMA2
//     register tiles (thread = 8 points x 8 channels), store s rows to g_s.
// ---------------------------------------------------------------------------
#define TP 128
#define HS 130   // sHt row stride (floats): even (LDS.64-aligned), low bank conflict

__global__ void __launch_bounds__(128) k_sgemm(
    const float* __restrict__ gf, const float* __restrict__ W0,
    const float* __restrict__ Ws, const float* __restrict__ bs, int N)
{
    __shared__ float sW[C_OUT * C_OUT];      // Ws[k][c]
    __shared__ float sHt[C_OUT * HS];        // sHt[k][pt] = h[p0+pt][k]

    const int tid  = threadIdx.x;
    const int lane = tid & 31;
    const int w    = tid >> 5;
    const int p0   = blockIdx.x * TP;

    // stage Ws into smem (coalesced float4)
#pragma unroll
    for (int i = tid; i < C_OUT * C_OUT / 4; i += 128)
        ((float4*)sW)[i] = __ldg((const float4*)Ws + i);

    // ---- h phase: warp w computes points p0 + w*32 .. +31; lane -> 2 ch ----
    {
        const int c0 = 2 * lane;
        u64 w0v[C_IN];
#pragma unroll
        for (int k = 0; k < C_IN; k++) {
            float2 ww = *(const float2*)(W0 + k * C_OUT + c0);
            w0v[k] = pk2(ww.x, ww.y);
        }
        const float2 a2 = *(const float2*)(g_a + c0);
        const float2 b2 = *(const float2*)(g_b + c0);
        const u64 av = pk2(a2.x, a2.y);
        const u64 bv = pk2(b2.x, b2.y);

#pragma unroll 2
        for (int j = 0; j < 32; j++) {
            const int pcol = w * 32 + j;
            const int p = p0 + pcol;
            u64 hv = 0;
            if (p < N) {
                const float2* xr = (const float2*)(gf + (long long)p * C_IN);
#pragma unroll
                for (int k2 = 0; k2 < C_IN / 2; k2++) {
                    float2 x2 = __ldg(xr + k2);
                    hv = fma2(pk2(x2.x, x2.x), w0v[2 * k2],     hv);
                    hv = fma2(pk2(x2.y, x2.y), w0v[2 * k2 + 1], hv);
                }
                hv = fma2(hv, av, bv);
            }
            float hx, hy; upk2(hv, hx, hy);
            hx = fmaxf(hx, 0.f);
            hy = fmaxf(hy, 0.f);
            sHt[c0 * HS + pcol]       = hx;
            sHt[(c0 + 1) * HS + pcol] = hy;
        }
    }
    __syncthreads();

    // ---- GEMM phase: thread (pg, cg) -> points pb..pb+7, channels cb..cb+7 --
    const int pg = tid >> 3;          // 0..15
    const int cg = tid & 7;           // 0..7
    const int pb = pg * 8;
    const int cb = cg * 8;

    u64 acc[4][8];
#pragma unroll
    for (int j = 0; j < 8; j++) {
        float bj = __ldg(bs + cb + j);
        u64 bjj = pk2(bj, bj);
#pragma unroll
        for (int i = 0; i < 4; i++) acc[i][j] = bjj;
    }

#pragma unroll
    for (int k = 0; k < C_OUT; k++) {
        u64 hp[4];
#pragma unroll
        for (int i = 0; i < 4; i++)
            hp[i] = *(const u64*)&sHt[k * HS + pb + 2 * i];
        float4 wA = *(const float4*)&sW[k * C_OUT + cb];
        float4 wB = *(const float4*)&sW[k * C_OUT + cb + 4];
        u64 wp[8];
        wp[0] = pk2(wA.x, wA.x); wp[1] = pk2(wA.y, wA.y);
        wp[2] = pk2(wA.z, wA.z); wp[3] = pk2(wA.w, wA.w);
        wp[4] = pk2(wB.x, wB.x); wp[5] = pk2(wB.y, wB.y);
        wp[6] = pk2(wB.z, wB.z); wp[7] = pk2(wB.w, wB.w);
#pragma unroll
        for (int i = 0; i < 4; i++)
#pragma unroll
            for (int j = 0; j < 8; j++)
                acc[i][j] = fma2(hp[i], wp[j], acc[i][j]);
    }

    // ---- store s (pre-relu): 2 points per acc row, 8 contiguous channels ----
#pragma unroll
    for (int i = 0; i < 4; i++) {
        float lo[8], hi[8];
#pragma unroll
        for (int j = 0; j < 8; j++) upk2(acc[i][j], lo[j], hi[j]);
        const long long pe = (long long)p0 + pb + 2 * i;
        if (pe < N) {
            float* d = g_s + pe * C_OUT + cb;
            *(float4*)(d)     = make_float4(lo[0], lo[1], lo[2], lo[3]);
            *(float4*)(d + 4) = make_float4(lo[4], lo[5], lo[6], lo[7]);
        }
        if (pe + 1 < N) {
            float* d = g_s + (pe + 1) * C_OUT + cb;
            *(float4*)(d)     = make_float4(hi[0], hi[1], hi[2], hi[3]);
            *(float4*)(d + 4) = make_float4(hi[4], hi[5], hi[6], hi[7]);
        }
    }
}

// ---------------------------------------------------------------------------
// K5: warp-per-pillar gather: read precomputed s row (coalesced), recompute
//     cheap h from x (uniform loads), single-exp online softmax, write canvas.
// ---------------------------------------------------------------------------
__global__ void __launch_bounds__(128) k_pillar(
    const float* __restrict__ gf, const int* __restrict__ pind,
    const float* __restrict__ W0, float* __restrict__ out, int M)
{
    const int lane = threadIdx.x & 31;
    const int pillar = blockIdx.x * 4 + (threadIdx.x >> 5);
    if (pillar >= M) return;
    const int c0 = 2 * lane;

    u64 w0v[C_IN];
#pragma unroll
    for (int k = 0; k < C_IN; k++) {
        float2 ww = *(const float2*)(W0 + k * C_OUT + c0);
        w0v[k] = pk2(ww.x, ww.y);
    }
    const float2 a2 = *(const float2*)(g_a + c0);
    const float2 b2 = *(const float2*)(g_b + c0);
    const u64 av = pk2(a2.x, a2.y);
    const u64 bv = pk2(b2.x, b2.y);

    const int cnt = min(g_cnt[pillar], MAXPTS);
    const int* __restrict__ ord = g_order + pillar * MAXPTS;

    float denx = 0.f, deny = 0.f;
    float numx = 0.f, numy = 0.f;
    float mxsx = 0.f, mxsy = 0.f;   // s >= 0 after relu
    float mxhx = 0.f, mxhy = 0.f;   // h >= 0 after relu

    // software pipeline: prefetch next point's id, s-pair, and x row
    int p_cur = (cnt > 0) ? __ldg(ord) : 0;
    float2 sv_cur = __ldg((const float2*)(g_s + (long long)p_cur * C_OUT) + lane);
    float2 x_cur[C_IN / 2];
    {
        const float2* xr = (const float2*)(gf + (long long)p_cur * C_IN);
#pragma unroll
        for (int k2 = 0; k2 < C_IN / 2; k2++) x_cur[k2] = __ldg(xr + k2);
    }

    for (int j = 0; j < cnt; j++) {
        float2 sv = sv_cur;
        float2 xv[C_IN / 2];
#pragma unroll
        for (int k2 = 0; k2 < C_IN / 2; k2++) xv[k2] = x_cur[k2];

        if (j + 1 < cnt) {
            int p_nxt = __ldg(ord + j + 1);
            sv_cur = __ldg((const float2*)(g_s + (long long)p_nxt * C_OUT) + lane);
            const float2* xr = (const float2*)(gf + (long long)p_nxt * C_IN);
#pragma unroll
            for (int k2 = 0; k2 < C_IN / 2; k2++) x_cur[k2] = __ldg(xr + k2);
        }

        // h = relu(BN(x @ W0)) for this lane's 2 channels
        u64 hv = 0;
#pragma unroll
        for (int k2 = 0; k2 < C_IN / 2; k2++) {
            hv = fma2(pk2(xv[k2].x, xv[k2].x), w0v[2 * k2],     hv);
            hv = fma2(pk2(xv[k2].y, xv[k2].y), w0v[2 * k2 + 1], hv);
        }
        hv = fma2(hv, av, bv);
        float hx, hy; upk2(hv, hx, hy);
        hx = fmaxf(hx, 0.f);
        hy = fmaxf(hy, 0.f);

        float s_x = fmaxf(sv.x, 0.f);
        float s_y = fmaxf(sv.y, 0.f);

        // single-exp online softmax
        {
            float d  = s_x - mxsx;
            float e1 = __expf(-fabsf(d));
            bool  gt = d > 0.f;
            float fa = gt ? e1 : 1.f;
            float fb = gt ? 1.f : e1;
            denx = fmaf(denx, fa, fb);
            numx = fmaf(numx, fa, fb * hx);
            mxsx = fmaxf(mxsx, s_x);
        }
        {
            float d  = s_y - mxsy;
            float e1 = __expf(-fabsf(d));
            bool  gt = d > 0.f;
            float fa = gt ? e1 : 1.f;
            float fb = gt ? 1.f : e1;
            deny = fmaf(deny, fa, fb);
            numy = fmaf(numy, fa, fb * hy);
            mxsy = fmaxf(mxsy, s_y);
        }
        mxhx = fmaxf(mxhx, hx);
        mxhy = fmaxf(mxhy, hy);
    }

    float pfx = 0.5f * (numx / denx + mxhx);
    float pfy = 0.5f * (numy / deny + mxhy);
    if (cnt == 0) { pfx = 0.f; pfy = 0.f; }

    const int b = __ldg(pind + pillar * 3 + 0);
    const int x = __ldg(pind + pillar * 3 + 1);
    const int y = __ldg(pind + pillar * 3 + 2);
    long long base = ((((long long)b * C_OUT + c0) * W_BEV + x) * H_BEV) + y;
    out[base] = pfx;
    out[base + (long long)W_BEV * H_BEV] = pfy;
}

// ---------------------------------------------------------------------------
extern "C" void kernel_launch(void* const* d_in, const int* in_sizes, int n_in,
                              void* d_out, int out_size)
{
    const float* gf    = (const float*)d_in[0];
    const int*   psi   = (const int*)  d_in[1];
    const int*   pind  = (const int*)  d_in[2];
    const float* W0    = (const float*)d_in[3];
    const float* gamma = (const float*)d_in[4];
    const float* beta  = (const float*)d_in[5];
    const float* Ws    = (const float*)d_in[6];
    const float* bs    = (const float*)d_in[7];
    float* out = (float*)d_out;

    const int N = in_sizes[0] / C_IN;
    const int M = in_sizes[2] / 3;

    k_init <<<4736, 256>>>((float4*)out, (long long)out_size / 4);
    k_stats<<<2048, 256>>>(gf, psi, W0, N);
    k_bn   <<<1, 64>>>(gamma, beta, 1.0f / (float)N);
    k_sgemm<<<(N + TP - 1) / TP, 128>>>(gf, W0, Ws, bs, N);
    k_pillar<<<(M + 3) / 4, 128>>>(gf, pind, W0, out, M);
}

// round 4
// speedup vs baseline: 1.8055x; 1.1015x over previous
#include <cuda_runtime.h>

#define C_IN   10
#define C_OUT  64
#define MAXM   200000
#define MAXN   2000000
#define MAXPTS 64
#define W_BEV  512
#define H_BEV  512
#define FULLMASK 0xffffffffu

// ---- device scratch (statics; no runtime allocation) ----
__device__ __align__(16) int   g_cnt[MAXM];
__device__ __align__(16) int   g_order[MAXM * MAXPTS];        // 51.2 MB
__device__ __align__(16) float g_s[(long long)MAXN * C_OUT];  // 512 MB
__device__ __align__(16) float g_xsum[C_IN];                  // sum of x
__device__ __align__(16) float g_xcov[55];                    // sum of x x^T (upper tri, i>=j)
__device__ __align__(16) float g_a[C_OUT];   // rstd*gamma
__device__ __align__(16) float g_b[C_OUT];   // beta - mu*rstd*gamma

// ---- packed f32x2 helpers ----
typedef unsigned long long u64;
__device__ __forceinline__ u64 pk2(float lo, float hi) {
    u64 r; asm("mov.b64 %0, {%1,%2};" : "=l"(r) : "f"(lo), "f"(hi)); return r;
}
__device__ __forceinline__ void upk2(u64 v, float& lo, float& hi) {
    asm("mov.b64 {%0,%1}, %2;" : "=f"(lo), "=f"(hi) : "l"(v));
}
__device__ __forceinline__ u64 fma2(u64 a, u64 b, u64 c) {
    u64 d; asm("fma.rn.f32x2 %0, %1, %2, %3;" : "=l"(d) : "l"(a), "l"(b), "l"(c)); return d;
}

// ---------------------------------------------------------------------------
// K1: zero canvas + counters + moment accumulators
// ---------------------------------------------------------------------------
__global__ void k_init(float4* __restrict__ out4, long long n4) {
    long long i = (long long)blockIdx.x * blockDim.x + threadIdx.x;
    long long stride = (long long)gridDim.x * blockDim.x;
    float4 z = make_float4(0.f, 0.f, 0.f, 0.f);
    for (long long j = i; j < n4; j += stride) out4[j] = z;
    int4* c4 = (int4*)g_cnt;
    for (long long j = i; j < MAXM / 4; j += stride) c4[j] = make_int4(0, 0, 0, 0);
    if (i < C_IN) g_xsum[i] = 0.f;
    if (i < 55)  g_xcov[i] = 0.f;
}

// ---------------------------------------------------------------------------
// K2: thread-per-point: bucket ids by pillar + accumulate x first/second
//     moments (BN stats via moment closure: stats of x@W0 from stats of x).
// ---------------------------------------------------------------------------
__global__ void __launch_bounds__(256) k_prep(
    const float* __restrict__ gf, const int* __restrict__ psi, int N)
{
    float sx[C_IN];
    float sxx[55];
#pragma unroll
    for (int i = 0; i < C_IN; i++) sx[i] = 0.f;
#pragma unroll
    for (int i = 0; i < 55; i++) sxx[i] = 0.f;

    const int stride = gridDim.x * blockDim.x;
    for (int p = blockIdx.x * blockDim.x + threadIdx.x; p < N; p += stride) {
        float x[C_IN];
        const float2* xr = (const float2*)(gf + (long long)p * C_IN);
#pragma unroll
        for (int k = 0; k < C_IN / 2; k++) {
            float2 v = __ldg(xr + k);
            x[2 * k] = v.x; x[2 * k + 1] = v.y;
        }
        int idx = __ldg(psi + p);
        int pos = atomicAdd(&g_cnt[idx], 1);
        if (pos < MAXPTS) g_order[idx * MAXPTS + pos] = p;
        int t = 0;
#pragma unroll
        for (int i = 0; i < C_IN; i++) {
            sx[i] += x[i];
#pragma unroll
            for (int j = 0; j <= i; j++) { sxx[t] = fmaf(x[i], x[j], sxx[t]); t++; }
        }
    }

    // warp reduce + lane0 atomic
    const int lane = threadIdx.x & 31;
#pragma unroll
    for (int i = 0; i < C_IN; i++) {
        float v = sx[i];
#pragma unroll
        for (int o = 16; o > 0; o >>= 1) v += __shfl_down_sync(FULLMASK, v, o);
        if (lane == 0) atomicAdd(&g_xsum[i], v);
    }
#pragma unroll
    for (int i = 0; i < 55; i++) {
        float v = sxx[i];
#pragma unroll
        for (int o = 16; o > 0; o >>= 1) v += __shfl_down_sync(FULLMASK, v, o);
        if (lane == 0) atomicAdd(&g_xcov[i], v);
    }
}

// ---------------------------------------------------------------------------
// K3: BN affine params from x moments: mu = xbar@W0 ; E[h^2] = w^T S w
// ---------------------------------------------------------------------------
__global__ void k_bn(const float* __restrict__ W0, const float* __restrict__ gamma,
                     const float* __restrict__ beta, float invN)
{
    int c = threadIdx.x;
    if (c < C_OUT) {
        float w[C_IN];
#pragma unroll
        for (int i = 0; i < C_IN; i++) w[i] = W0[i * C_OUT + c];
        float mu = 0.f;
#pragma unroll
        for (int i = 0; i < C_IN; i++) mu = fmaf(g_xsum[i] * invN, w[i], mu);
        float ex2 = 0.f;
        int t = 0;
#pragma unroll
        for (int i = 0; i < C_IN; i++) {
#pragma unroll
            for (int j = 0; j <= i; j++) {
                float s = g_xcov[t++] * invN;
                float coef = (i == j) ? 1.f : 2.f;
                ex2 = fmaf(coef * s, w[i] * w[j], ex2);
            }
        }
        float var = fmaf(-mu, mu, ex2);
        float rstd = rsqrtf(var + 1e-3f);
        float a = rstd * gamma[c];
        g_a[c] = a;
        g_b[c] = fmaf(-mu, a, beta[c]);
    }
}

// ---------------------------------------------------------------------------
// K4: dense s = h@Ws + bs (h = relu(BN(x@W0)) recomputed into smem).
//     h-phase: lane owns channels (lane, lane+32), paired-point float2 stores
//     (4-way conflicts instead of 8-way). GEMM: thread = 8pts x 8ch FFMA2,
//     h loaded as ulonglong2 (LDS.128, FMA2-ready pairs).
// ---------------------------------------------------------------------------
#define TP 128
#define HS 132   // multiple of 4 (16B-aligned rows)

__global__ void __launch_bounds__(128) k_sgemm(
    const float* __restrict__ gf, const float* __restrict__ W0,
    const float* __restrict__ Ws, const float* __restrict__ bs, int N)
{
    __shared__ __align__(16) float sW[C_OUT * C_OUT];
    __shared__ __align__(16) float sHt[C_OUT * HS];

    const int tid  = threadIdx.x;
    const int lane = tid & 31;
    const int w    = tid >> 5;
    const int p0   = blockIdx.x * TP;

#pragma unroll
    for (int i = tid; i < C_OUT * C_OUT / 4; i += 128)
        ((float4*)sW)[i] = __ldg((const float4*)Ws + i);

    // ---- h phase ----
    {
        const int cA = lane, cB = lane + 32;
        u64 w0v[C_IN];
#pragma unroll
        for (int k = 0; k < C_IN; k++)
            w0v[k] = pk2(__ldg(W0 + k * C_OUT + cA), __ldg(W0 + k * C_OUT + cB));
        const u64 av = pk2(g_a[cA], g_a[cB]);
        const u64 bv = pk2(g_b[cA], g_b[cB]);

#pragma unroll 2
        for (int j = 0; j < 32; j += 2) {
            const int pcol = w * 32 + j;
            const int p = p0 + pcol;
            u64 hv0 = 0, hv1 = 0;
            if (p < N) {
                const float2* xr = (const float2*)(gf + (long long)p * C_IN);
#pragma unroll
                for (int k2 = 0; k2 < C_IN / 2; k2++) {
                    float2 x2 = __ldg(xr + k2);
                    hv0 = fma2(pk2(x2.x, x2.x), w0v[2 * k2],     hv0);
                    hv0 = fma2(pk2(x2.y, x2.y), w0v[2 * k2 + 1], hv0);
                }
                hv0 = fma2(hv0, av, bv);
            }
            if (p + 1 < N) {
                const float2* xr = (const float2*)(gf + (long long)(p + 1) * C_IN);
#pragma unroll
                for (int k2 = 0; k2 < C_IN / 2; k2++) {
                    float2 x2 = __ldg(xr + k2);
                    hv1 = fma2(pk2(x2.x, x2.x), w0v[2 * k2],     hv1);
                    hv1 = fma2(pk2(x2.y, x2.y), w0v[2 * k2 + 1], hv1);
                }
                hv1 = fma2(hv1, av, bv);
            }
            float hA0, hB0, hA1, hB1;
            upk2(hv0, hA0, hB0); upk2(hv1, hA1, hB1);
            hA0 = fmaxf(hA0, 0.f); hB0 = fmaxf(hB0, 0.f);
            hA1 = fmaxf(hA1, 0.f); hB1 = fmaxf(hB1, 0.f);
            *(float2*)&sHt[cA * HS + pcol] = make_float2(hA0, hA1);
            *(float2*)&sHt[cB * HS + pcol] = make_float2(hB0, hB1);
        }
    }
    __syncthreads();

    // ---- GEMM phase ----
    const int pg = tid >> 3;
    const int cg = tid & 7;
    const int pb = pg * 8;
    const int cb = cg * 8;

    u64 acc[4][8];
#pragma unroll
    for (int j = 0; j < 8; j++) {
        float bj = __ldg(bs + cb + j);
        u64 bjj = pk2(bj, bj);
#pragma unroll
        for (int i = 0; i < 4; i++) acc[i][j] = bjj;
    }

#pragma unroll
    for (int k = 0; k < C_OUT; k += 2) {
        const float* r0 = &sHt[k * HS + pb];
        ulonglong2 ha = *(const ulonglong2*)r0;
        ulonglong2 hb = *(const ulonglong2*)(r0 + 4);
        ulonglong2 hc = *(const ulonglong2*)(r0 + HS);
        ulonglong2 hd = *(const ulonglong2*)(r0 + HS + 4);
        u64 hp0[4] = {ha.x, ha.y, hb.x, hb.y};
        u64 hp1[4] = {hc.x, hc.y, hd.x, hd.y};

        float4 wA0 = *(const float4*)&sW[k * C_OUT + cb];
        float4 wB0 = *(const float4*)&sW[k * C_OUT + cb + 4];
        float4 wA1 = *(const float4*)&sW[(k + 1) * C_OUT + cb];
        float4 wB1 = *(const float4*)&sW[(k + 1) * C_OUT + cb + 4];
        u64 w0p[8] = {pk2(wA0.x,wA0.x), pk2(wA0.y,wA0.y), pk2(wA0.z,wA0.z), pk2(wA0.w,wA0.w),
                      pk2(wB0.x,wB0.x), pk2(wB0.y,wB0.y), pk2(wB0.z,wB0.z), pk2(wB0.w,wB0.w)};
        u64 w1p[8] = {pk2(wA1.x,wA1.x), pk2(wA1.y,wA1.y), pk2(wA1.z,wA1.z), pk2(wA1.w,wA1.w),
                      pk2(wB1.x,wB1.x), pk2(wB1.y,wB1.y), pk2(wB1.z,wB1.z), pk2(wB1.w,wB1.w)};
#pragma unroll
        for (int i = 0; i < 4; i++)
#pragma unroll
            for (int j = 0; j < 8; j++)
                acc[i][j] = fma2(hp0[i], w0p[j], acc[i][j]);
#pragma unroll
        for (int i = 0; i < 4; i++)
#pragma unroll
            for (int j = 0; j < 8; j++)
                acc[i][j] = fma2(hp1[i], w1p[j], acc[i][j]);
    }

    // ---- store s (pre-relu) ----
#pragma unroll
    for (int i = 0; i < 4; i++) {
        float lo[8], hi[8];
#pragma unroll
        for (int j = 0; j < 8; j++) upk2(acc[i][j], lo[j], hi[j]);
        const long long pe = (long long)p0 + pb + 2 * i;
        if (pe < N) {
            float* d = g_s + pe * C_OUT + cb;
            *(float4*)(d)     = make_float4(lo[0], lo[1], lo[2], lo[3]);
            *(float4*)(d + 4) = make_float4(lo[4], lo[5], lo[6], lo[7]);
        }
        if (pe + 1 < N) {
            float* d = g_s + (pe + 1) * C_OUT + cb;
            *(float4*)(d)     = make_float4(hi[0], hi[1], hi[2], hi[3]);
            *(float4*)(d + 4) = make_float4(hi[4], hi[5], hi[6], hi[7]);
        }
    }
}

// ---------------------------------------------------------------------------
// K5: warp-per-pillar gather with ord preloaded into lane regs and
//     depth-2 double-buffered prefetch of s rows + x rows.
// ---------------------------------------------------------------------------
struct Acc { float den, num, mxs, mxh; };

__device__ __forceinline__ void soft_step(Acc& a, float s, float h) {
    float d  = s - a.mxs;
    float e1 = __expf(-fabsf(d));
    bool  gt = d > 0.f;
    float fa = gt ? e1 : 1.f;
    float fb = gt ? 1.f : e1;
    a.den = fmaf(a.den, fa, fb);
    a.num = fmaf(a.num, fa, fb * h);
    a.mxs = fmaxf(a.mxs, s);
    a.mxh = fmaxf(a.mxh, h);
}

__global__ void __launch_bounds__(128) k_pillar(
    const float* __restrict__ gf, const int* __restrict__ pind,
    const float* __restrict__ W0, float* __restrict__ out, int M)
{
    const int lane = threadIdx.x & 31;
    const int pillar = blockIdx.x * 4 + (threadIdx.x >> 5);
    if (pillar >= M) return;
    const int c0 = 2 * lane;

    u64 w0v[C_IN];
#pragma unroll
    for (int k = 0; k < C_IN; k++) {
        float2 ww = *(const float2*)(W0 + k * C_OUT + c0);
        w0v[k] = pk2(ww.x, ww.y);
    }
    const float2 a2 = *(const float2*)(g_a + c0);
    const float2 b2 = *(const float2*)(g_b + c0);
    const u64 av = pk2(a2.x, a2.y);
    const u64 bv = pk2(b2.x, b2.y);

    const int cnt = min(g_cnt[pillar], MAXPTS);
    const int* __restrict__ ord = g_order + pillar * MAXPTS;
    const int myp0 = __ldg(ord + lane);
    const int myp1 = __ldg(ord + 32 + lane);

    Acc aX = {0.f, 0.f, 0.f, 0.f};
    Acc aY = {0.f, 0.f, 0.f, 0.f};

    float2 sv0, sv1;
    float2 xv0[C_IN / 2], xv1[C_IN / 2];

#define GETP(j)  __shfl_sync(FULLMASK, ((j) < 32 ? myp0 : myp1), (j) & 31)
#define PREF(SV, XV, j) { \
        int _p = GETP(j); \
        SV = __ldg((const float2*)(g_s + (long long)_p * C_OUT) + lane); \
        const float2* _xr = (const float2*)(gf + (long long)_p * C_IN); \
        _Pragma("unroll") \
        for (int _k = 0; _k < C_IN / 2; _k++) XV[_k] = __ldg(_xr + _k); }

#define BODY(SV, XV, j) { \
        u64 hv = 0; \
        _Pragma("unroll") \
        for (int _k = 0; _k < C_IN / 2; _k++) { \
            hv = fma2(pk2(XV[_k].x, XV[_k].x), w0v[2 * _k],     hv); \
            hv = fma2(pk2(XV[_k].y, XV[_k].y), w0v[2 * _k + 1], hv); \
        } \
        hv = fma2(hv, av, bv); \
        float hx, hy; upk2(hv, hx, hy); \
        hx = fmaxf(hx, 0.f); hy = fmaxf(hy, 0.f); \
        float s_x = fmaxf(SV.x, 0.f), s_y = fmaxf(SV.y, 0.f); \
        soft_step(aX, s_x, hx); \
        soft_step(aY, s_y, hy); }

    if (cnt > 0) PREF(sv0, xv0, 0);
    if (cnt > 1) PREF(sv1, xv1, 1);

    int j = 0;
    while (j < cnt) {
        BODY(sv0, xv0, j);
        if (j + 2 < cnt) PREF(sv0, xv0, j + 2);
        j++;
        if (j >= cnt) break;
        BODY(sv1, xv1, j);
        if (j + 2 < cnt) PREF(sv1, xv1, j + 2);
        j++;
    }

    float pfx = 0.5f * (aX.num / aX.den + aX.mxh);
    float pfy = 0.5f * (aY.num / aY.den + aY.mxh);
    if (cnt == 0) { pfx = 0.f; pfy = 0.f; }

    const int b = __ldg(pind + pillar * 3 + 0);
    const int x = __ldg(pind + pillar * 3 + 1);
    const int y = __ldg(pind + pillar * 3 + 2);
    long long base = ((((long long)b * C_OUT + c0) * W_BEV + x) * H_BEV) + y;
    out[base] = pfx;
    out[base + (long long)W_BEV * H_BEV] = pfy;
}

// ---------------------------------------------------------------------------
extern "C" void kernel_launch(void* const* d_in, const int* in_sizes, int n_in,
                              void* d_out, int out_size)
{
    const float* gf    = (const float*)d_in[0];
    const int*   psi   = (const int*)  d_in[1];
    const int*   pind  = (const int*)  d_in[2];
    const float* W0    = (const float*)d_in[3];
    const float* gamma = (const float*)d_in[4];
    const float* beta  = (const float*)d_in[5];
    const float* Ws    = (const float*)d_in[6];
    const float* bs    = (const float*)d_in[7];
    float* out = (float*)d_out;

    const int N = in_sizes[0] / C_IN;
    const int M = in_sizes[2] / 3;

    k_init <<<4736, 256>>>((float4*)out, (long long)out_size / 4);
    k_prep <<<1480, 256>>>(gf, psi, N);
    k_bn   <<<1, 64>>>(W0, gamma, beta, 1.0f / (float)N);
    k_sgemm<<<(N + TP - 1) / TP, 128>>>(gf, W0, Ws, bs, N);
    k_pillar<<<(M + 3) / 4, 128>>>(gf, pind, W0, out, M);
}